// round 10
// baseline (speedup 1.0000x reference)
#include <cuda_runtime.h>

#define KNN      11
#define NPTS     50000
#define NSP      4000
#define NB       2
#define G        20
#define NCELL    (G*G*G)                  // 8000
#define CHUNK    ((NCELL + 255) / 256)    // 32
#define TMAIN    256
#define BLKS_MAIN ((NPTS + TMAIN - 1) / TMAIN)
#define SENT     0x7FFFFFFF

// ---------------- device scratch (no allocations allowed) ----------------
__device__ float4         g_spk[NB][NSP];       // cell-sorted sites, w = int_as_float(sidx<<12)
__device__ unsigned short g_cst[NB][NCELL + 1]; // site cell start offsets
__device__ float          g_box[NB][9];         // mn[3], h[3], inv_h[3]
__device__ int            g_pcnt[NB][NCELL];
__device__ int            g_pcur[NB][NCELL];
__device__ float4         g_pts[NB][NPTS];      // cell-sorted queries (w = orig idx)

__device__ __forceinline__ int cell_of(float x, float y, float z, const float* bx) {
    int cx = (int)((x - bx[0]) * bx[6]); cx = min(G - 1, max(0, cx));
    int cy = (int)((y - bx[1]) * bx[7]); cy = min(G - 1, max(0, cy));
    int cz = (int)((z - bx[2]) * bx[8]); cz = min(G - 1, max(0, cz));
    return (cx * G + cy) * G + cz;
}

// ---------------- kernel 1: bin sites into grid (one block per batch) ----------------
static constexpr int SM_SETUP = (NCELL + NCELL + 1 + 256) * 4 + 48 * 4;

__global__ void k_setup_sites(const float* __restrict__ spoints) {
    extern __shared__ int sm[];
    int*   cnt = sm;                  // NCELL
    int*   st  = cnt + NCELL;         // NCELL+1
    int*   tot = st + NCELL + 1;      // 256
    float* red = (float*)(tot + 256); // 48
    __shared__ float sbox[9];

    const int b = blockIdx.x, tid = threadIdx.x;
    const float* sp = spoints + (size_t)b * NSP * 3;

    for (int c = tid; c < NCELL; c += blockDim.x) g_pcnt[b][c] = 0;

    float mnx = 3e38f, mny = 3e38f, mnz = 3e38f;
    float mxx = -3e38f, mxy = -3e38f, mxz = -3e38f;
    for (int i = tid; i < NSP; i += blockDim.x) {
        float x = sp[3*i], y = sp[3*i+1], z = sp[3*i+2];
        mnx = fminf(mnx, x); mxx = fmaxf(mxx, x);
        mny = fminf(mny, y); mxy = fmaxf(mxy, y);
        mnz = fminf(mnz, z); mxz = fmaxf(mxz, z);
    }
#pragma unroll
    for (int o = 16; o; o >>= 1) {
        mnx = fminf(mnx, __shfl_xor_sync(0xffffffffu, mnx, o));
        mny = fminf(mny, __shfl_xor_sync(0xffffffffu, mny, o));
        mnz = fminf(mnz, __shfl_xor_sync(0xffffffffu, mnz, o));
        mxx = fmaxf(mxx, __shfl_xor_sync(0xffffffffu, mxx, o));
        mxy = fmaxf(mxy, __shfl_xor_sync(0xffffffffu, mxy, o));
        mxz = fmaxf(mxz, __shfl_xor_sync(0xffffffffu, mxz, o));
    }
    int w = tid >> 5;
    if ((tid & 31) == 0) {
        red[w] = mnx; red[8 + w] = mny; red[16 + w] = mnz;
        red[24 + w] = mxx; red[32 + w] = mxy; red[40 + w] = mxz;
    }
    __syncthreads();
    if (tid == 0) {
        float a0 = red[0], a1 = red[8], a2 = red[16], a3 = red[24], a4 = red[32], a5 = red[40];
        for (int i = 1; i < 8; i++) {
            a0 = fminf(a0, red[i]);      a1 = fminf(a1, red[8 + i]);  a2 = fminf(a2, red[16 + i]);
            a3 = fmaxf(a3, red[24 + i]); a4 = fmaxf(a4, red[32 + i]); a5 = fmaxf(a5, red[40 + i]);
        }
        float hx = (a3 - a0) * (1.0f / G) * 1.000001f + 1e-30f;
        float hy = (a4 - a1) * (1.0f / G) * 1.000001f + 1e-30f;
        float hz = (a5 - a2) * (1.0f / G) * 1.000001f + 1e-30f;
        sbox[0] = a0; sbox[1] = a1; sbox[2] = a2;
        sbox[3] = hx; sbox[4] = hy; sbox[5] = hz;
        sbox[6] = 1.0f / hx; sbox[7] = 1.0f / hy; sbox[8] = 1.0f / hz;
        for (int i = 0; i < 9; i++) g_box[b][i] = sbox[i];
    }
    __syncthreads();

    for (int c = tid; c < NCELL; c += blockDim.x) cnt[c] = 0;
    __syncthreads();
    for (int i = tid; i < NSP; i += blockDim.x) {
        int c = cell_of(sp[3*i], sp[3*i+1], sp[3*i+2], sbox);
        atomicAdd(&cnt[c], 1);
    }
    __syncthreads();

    int c0 = tid * CHUNK, s = 0;
    for (int j = 0; j < CHUNK; j++) { int c = c0 + j; if (c < NCELL) s += cnt[c]; }
    tot[tid] = s;
    __syncthreads();
    if (tid == 0) { int run = 0; for (int i = 0; i < 256; i++) { int v = tot[i]; tot[i] = run; run += v; } }
    __syncthreads();
    int run = tot[tid];
    for (int j = 0; j < CHUNK; j++) { int c = c0 + j; if (c < NCELL) { st[c] = run; run += cnt[c]; } }
    __syncthreads();
    if (tid == 0) st[NCELL] = NSP;
    __syncthreads();

    for (int c = tid; c <= NCELL; c += blockDim.x) g_cst[b][c] = (unsigned short)st[c];
    for (int c = tid; c < NCELL; c += blockDim.x) cnt[c] = st[c];   // cnt becomes cursor
    __syncthreads();

    for (int i = tid; i < NSP; i += blockDim.x) {
        float x = sp[3*i], y = sp[3*i+1], z = sp[3*i+2];
        int c = cell_of(x, y, z, sbox);
        int pos = atomicAdd(&cnt[c], 1);
        g_spk[b][pos] = make_float4(x, y, z, __int_as_float(i << 12));
    }
}

// ---------------- kernel 2: count queries per cell ----------------
__global__ void k_count_pts(const float* __restrict__ points) {
    const int b = blockIdx.y;
    const int p = blockIdx.x * blockDim.x + threadIdx.x;
    if (p >= NPTS) return;
    const float* pp = points + ((size_t)b * NPTS + p) * 3;
    float bx[9];
#pragma unroll
    for (int i = 0; i < 9; i++) bx[i] = g_box[b][i];
    atomicAdd(&g_pcnt[b][cell_of(pp[0], pp[1], pp[2], bx)], 1);
}

// ---------------- kernel 3: scan query counts -> cursors ----------------
__global__ void k_init_cursors() {
    const int b = blockIdx.x, tid = threadIdx.x;
    __shared__ int tot[256];
    int c0 = tid * CHUNK, s = 0;
    for (int j = 0; j < CHUNK; j++) { int c = c0 + j; if (c < NCELL) s += g_pcnt[b][c]; }
    tot[tid] = s;
    __syncthreads();
    if (tid == 0) { int run = 0; for (int i = 0; i < 256; i++) { int v = tot[i]; tot[i] = run; run += v; } }
    __syncthreads();
    int run = tot[tid];
    for (int j = 0; j < CHUNK; j++) { int c = c0 + j; if (c < NCELL) { g_pcur[b][c] = run; run += g_pcnt[b][c]; } }
}

// ---------------- kernel 4: scatter queries into cell-sorted order ----------------
__global__ void k_scatter_pts(const float* __restrict__ points) {
    const int b = blockIdx.y;
    const int p = blockIdx.x * blockDim.x + threadIdx.x;
    if (p >= NPTS) return;
    const float* pp = points + ((size_t)b * NPTS + p) * 3;
    float x = pp[0], y = pp[1], z = pp[2];
    float bx[9];
#pragma unroll
    for (int i = 0; i < 9; i++) bx[i] = g_box[b][i];
    int pos = atomicAdd(&g_pcur[b][cell_of(x, y, z, bx)], 1);
    g_pts[b][pos] = make_float4(x, y, z, __int_as_float(p));
}

// ---------------- kernel 5: main — warp-per-query cooperative KNN ----------------
static constexpr int SM_MAIN = NSP * 16 + 16 * 4 + (NCELL + 1) * 2;  // 80066

__global__ __launch_bounds__(TMAIN, 2) void k_main(float* __restrict__ out) {
    extern __shared__ float smf[];
    float4* spk = (float4*)smf;                        // NSP float4
    float*  sbb = (float*)(spk + NSP);                 // 9 floats (+pad)
    unsigned short* cst = (unsigned short*)(sbb + 16); // NCELL+1

    const int b = blockIdx.y, tid = threadIdx.x;
    for (int i = tid; i < NSP; i += TMAIN) spk[i] = g_spk[b][i];
    for (int i = tid; i <= NCELL; i += TMAIN) cst[i] = g_cst[b][i];
    if (tid < 9) sbb[tid] = g_box[b][tid];
    __syncthreads();

    const int lane = tid & 31;
    int t = blockIdx.x * TMAIN + tid;
    const bool valid = (t < NPTS);
    if (!valid) t = NPTS - 1;            // duplicate last point; keeps warp full

    const float4 P = g_pts[b][t];
    const float px = P.x, py = P.y, pz = P.z;
    const int orig = __float_as_int(P.w);

    const float mnx = sbb[0], mny = sbb[1], mnz = sbb[2];
    const float hx = sbb[3], hy = sbb[4], hz = sbb[5];
    const float ihx = sbb[6], ihy = sbb[7], ihz = sbb[8];
    const int cx = min(G - 1, max(0, (int)((px - mnx) * ihx)));
    const int cy = min(G - 1, max(0, (int)((py - mny) * ihy)));
    const int cz = min(G - 1, max(0, (int)((pz - mnz) * ihz)));

    // ---- Phase A (per lane, for its own query): count box -> T and window ----
    int xlo, xhi, ylo, yhi, zlo, zhi;
    for (int r = 0; ; r++) {
        xlo = max(cx - r, 0); xhi = min(cx + r, G - 1);
        ylo = max(cy - r, 0); yhi = min(cy + r, G - 1);
        zlo = max(cz - r, 0); zhi = min(cz + r, G - 1);
        int count = 0;
        for (int X = xlo; X <= xhi; X++) {
            const int rb = X * G;
            for (int Y = ylo; Y <= yhi; Y++) {
                const int cb = (rb + Y) * G;
                count += (int)cst[cb + zhi + 1] - (int)cst[cb + zlo];
            }
        }
        if (count >= KNN) break;
        if (xlo == 0 && xhi == G - 1 && ylo == 0 && yhi == G - 1 &&
            zlo == 0 && zhi == G - 1) break;
    }
    const float fx = fmaxf(px - (mnx + (float)xlo * hx), (mnx + (float)(xhi + 1) * hx) - px);
    const float fy = fmaxf(py - (mny + (float)ylo * hy), (mny + (float)(yhi + 1) * hy) - py);
    const float fz = fmaxf(pz - (mnz + (float)zlo * hz), (mnz + (float)(zhi + 1) * hz) - pz);
    const float T  = (fmaf(fx, fx, fmaf(fy, fy, fz * fz))) * 1.0005f;  // fp-safe upper bound on d2_11
    const float sT = sqrtf(T);

    const int qxl = min(G - 1, max(0, (int)((px - sT - mnx) * ihx)));
    const int qxh = min(G - 1, max(0, (int)((px + sT - mnx) * ihx)));
    const int qyl = min(G - 1, max(0, (int)((py - sT - mny) * ihy)));
    const int qyh = min(G - 1, max(0, (int)((py + sT - mny) * ihy)));
    const int qzl = min(G - 1, max(0, (int)((pz - sT - mnz) * ihz)));
    const int qzh = min(G - 1, max(0, (int)((pz + sT - mnz) * ihz)));
    const unsigned wpack = (unsigned)qxl | ((unsigned)qxh << 5) |
                           ((unsigned)qyl << 10) | ((unsigned)qyh << 15) |
                           ((unsigned)qzl << 20) | ((unsigned)qzh << 25);

    const unsigned FULL = 0xffffffffu;
    float myout = 0.0f;

    // ---- process the warp's 32 queries, one at a time, all lanes cooperating ----
#pragma unroll 1
    for (int j = 0; j < 32; j++) {
        const float qx = __shfl_sync(FULL, px, j);
        const float qy = __shfl_sync(FULL, py, j);
        const float qz = __shfl_sync(FULL, pz, j);
        const float Tj = __shfl_sync(FULL, T, j);
        const unsigned wj = __shfl_sync(FULL, wpack, j);
        const int xl = wj & 31, xh = (wj >> 5) & 31;
        const int yl = (wj >> 10) & 31, yh = (wj >> 15) & 31;
        const int zl = (wj >> 20) & 31, zh = (wj >> 25) & 31;

        // lane-local sorted top-11, sentinel-filled with (Tj, SENT)
        float bd[KNN];
        int   bo[KNN];
#pragma unroll
        for (int k = 0; k < KNN; k++) { bd[k] = Tj; bo[k] = SENT; }

        // uniform column sweep; candidates striped across lanes
        for (int X = xl; X <= xh; X++) {
            for (int Y = yl; Y <= yh; Y++) {
                const int cb = (X * G + Y) * G;
                const int m0 = cst[cb + zl], m1 = cst[cb + zh + 1];  // uniform broadcast
                for (int m = m0 + lane; m < m1; m += 32) {
                    const float4 S = spk[m];
                    const float dx = qx - S.x;
                    const float dy = qy - S.y;
                    const float dz = qz - S.z;
                    const float d2 = fmaf(dz, dz, fmaf(dy, dy, dx * dx));
                    if (d2 <= bd[KNN - 1]) {
                        float d = d2;
                        int kk = __float_as_int(S.w) | m;
#pragma unroll
                        for (int k = 0; k < KNN; k++) {
                            const bool sw = (d < bd[k]) || ((d == bd[k]) && (kk < bo[k]));
                            if (sw) {
                                const float td = bd[k]; bd[k] = d;  d = td;
                                const int   ti = bo[k]; bo[k] = kk; kk = ti;
                            }
                        }
                    }
                }
            }
        }

        // 11-round warp tournament merge: exact (d2, key) lex order
        int mym = 0;
#pragma unroll
        for (int k = 0; k < KNN; k++) {
            const unsigned db   = __float_as_uint(bd[0]);       // d2 >= 0: bits are ordered
            const unsigned minb = __reduce_min_sync(FULL, db);
            const unsigned ck   = (db == minb) ? (unsigned)bo[0] : 0xFFFFFFFFu;
            const unsigned mink = __reduce_min_sync(FULL, ck);
            const bool win = (db == minb) && (ck == mink);      // unique: site keys unique
            if (win) {                                          // pop: shift list down
#pragma unroll
                for (int s = 0; s < KNN - 1; s++) { bd[s] = bd[s + 1]; bo[s] = bo[s + 1]; }
                bd[KNN - 1] = 3.4e38f; bo[KNN - 1] = SENT;
            }
            if (lane == k) mym = (int)(mink & 4095u);           // lane k holds k-th NN site pos
        }

        // Voronoi-edge epilogue: lanes 1..10 compute one edge each, warp-min
        const int m0c = __shfl_sync(FULL, mym, 0);
        const float4 C = spk[m0c];
        float val = 3.4e38f;
        if (lane >= 1 && lane <= 10) {
            const float4 E = spk[mym];
            const float ex = E.x - C.x, ey = E.y - C.y, ez = E.z - C.z;
            const float el2 = fmaf(ez, ez, fmaf(ey, ey, ex * ex));
            const float tx = qx - C.x, ty = qy - C.y, tz = qz - C.z;
            const float dp = fmaf(tz, ez, fmaf(ty, ey, tx * ex));
            const float tt = fmaf(-0.5f, el2, dp) * rsqrtf(el2);   // (dp - el2/2)/sqrt(el2)
            val = tt * tt;
        }
        const unsigned vmin = __reduce_min_sync(FULL, __float_as_uint(val));  // val >= 0
        if (lane == j) myout = __uint_as_float(vmin);
    }

    if (valid) out[(size_t)b * NPTS + orig] = myout;
}

// ---------------- launch ----------------
extern "C" void kernel_launch(void* const* d_in, const int* in_sizes, int n_in,
                              void* d_out, int out_size)
{
    const float* points  = (const float*)d_in[0];
    const float* spoints = (const float*)d_in[1];
    float* out = (float*)d_out;

    cudaFuncSetAttribute(k_setup_sites, cudaFuncAttributeMaxDynamicSharedMemorySize, SM_SETUP);
    cudaFuncSetAttribute(k_main,        cudaFuncAttributeMaxDynamicSharedMemorySize, SM_MAIN);

    k_setup_sites<<<NB, 256, SM_SETUP>>>(spoints);
    dim3 gp((NPTS + 255) / 256, NB);
    k_count_pts<<<gp, 256>>>(points);
    k_init_cursors<<<NB, 256>>>();
    k_scatter_pts<<<gp, 256>>>(points);
    k_main<<<dim3(BLKS_MAIN, NB), TMAIN, SM_MAIN>>>(out);
}

// round 11
// speedup vs baseline: 3.0675x; 3.0675x over previous
#include <cuda_runtime.h>

#define KNN      11
#define NPTS     50000
#define NSP      4000
#define NB       2
#define G        20
#define NCELL    (G*G*G)                  // 8000
#define CHUNK    ((NCELL + 255) / 256)    // 32
#define TMAIN    256
#define BLKS_MAIN ((NPTS + TMAIN - 1) / TMAIN)
#define SENT     0x7FFFFFFF

// ---------------- device scratch (no allocations allowed) ----------------
__device__ float4         g_spk[NB][NSP];       // cell-sorted sites, w = int_as_float(sidx<<12)
__device__ unsigned short g_cst[NB][NCELL + 1]; // site cell start offsets
__device__ float          g_box[NB][9];         // mn[3], h[3], inv_h[3]
__device__ int            g_pcnt[NB][NCELL];
__device__ int            g_pcur[NB][NCELL];
__device__ float4         g_pts[NB][NPTS];      // cell-sorted queries (w = orig idx)

__device__ __forceinline__ int cell_of(float x, float y, float z, const float* bx) {
    int cx = (int)((x - bx[0]) * bx[6]); cx = min(G - 1, max(0, cx));
    int cy = (int)((y - bx[1]) * bx[7]); cy = min(G - 1, max(0, cy));
    int cz = (int)((z - bx[2]) * bx[8]); cz = min(G - 1, max(0, cz));
    return (cx * G + cy) * G + cz;
}

// ---------------- kernel 1: bin sites into grid (one block per batch) ----------------
static constexpr int SM_SETUP = (NCELL + NCELL + 1 + 256) * 4 + 48 * 4;

__global__ void k_setup_sites(const float* __restrict__ spoints) {
    extern __shared__ int sm[];
    int*   cnt = sm;                  // NCELL
    int*   st  = cnt + NCELL;         // NCELL+1
    int*   tot = st + NCELL + 1;      // 256
    float* red = (float*)(tot + 256); // 48
    __shared__ float sbox[9];

    const int b = blockIdx.x, tid = threadIdx.x;
    const float* sp = spoints + (size_t)b * NSP * 3;

    for (int c = tid; c < NCELL; c += blockDim.x) g_pcnt[b][c] = 0;

    float mnx = 3e38f, mny = 3e38f, mnz = 3e38f;
    float mxx = -3e38f, mxy = -3e38f, mxz = -3e38f;
    for (int i = tid; i < NSP; i += blockDim.x) {
        float x = sp[3*i], y = sp[3*i+1], z = sp[3*i+2];
        mnx = fminf(mnx, x); mxx = fmaxf(mxx, x);
        mny = fminf(mny, y); mxy = fmaxf(mxy, y);
        mnz = fminf(mnz, z); mxz = fmaxf(mxz, z);
    }
#pragma unroll
    for (int o = 16; o; o >>= 1) {
        mnx = fminf(mnx, __shfl_xor_sync(0xffffffffu, mnx, o));
        mny = fminf(mny, __shfl_xor_sync(0xffffffffu, mny, o));
        mnz = fminf(mnz, __shfl_xor_sync(0xffffffffu, mnz, o));
        mxx = fmaxf(mxx, __shfl_xor_sync(0xffffffffu, mxx, o));
        mxy = fmaxf(mxy, __shfl_xor_sync(0xffffffffu, mxy, o));
        mxz = fmaxf(mxz, __shfl_xor_sync(0xffffffffu, mxz, o));
    }
    int w = tid >> 5;
    if ((tid & 31) == 0) {
        red[w] = mnx; red[8 + w] = mny; red[16 + w] = mnz;
        red[24 + w] = mxx; red[32 + w] = mxy; red[40 + w] = mxz;
    }
    __syncthreads();
    if (tid == 0) {
        float a0 = red[0], a1 = red[8], a2 = red[16], a3 = red[24], a4 = red[32], a5 = red[40];
        for (int i = 1; i < 8; i++) {
            a0 = fminf(a0, red[i]);      a1 = fminf(a1, red[8 + i]);  a2 = fminf(a2, red[16 + i]);
            a3 = fmaxf(a3, red[24 + i]); a4 = fmaxf(a4, red[32 + i]); a5 = fmaxf(a5, red[40 + i]);
        }
        float hx = (a3 - a0) * (1.0f / G) * 1.000001f + 1e-30f;
        float hy = (a4 - a1) * (1.0f / G) * 1.000001f + 1e-30f;
        float hz = (a5 - a2) * (1.0f / G) * 1.000001f + 1e-30f;
        sbox[0] = a0; sbox[1] = a1; sbox[2] = a2;
        sbox[3] = hx; sbox[4] = hy; sbox[5] = hz;
        sbox[6] = 1.0f / hx; sbox[7] = 1.0f / hy; sbox[8] = 1.0f / hz;
        for (int i = 0; i < 9; i++) g_box[b][i] = sbox[i];
    }
    __syncthreads();

    for (int c = tid; c < NCELL; c += blockDim.x) cnt[c] = 0;
    __syncthreads();
    for (int i = tid; i < NSP; i += blockDim.x) {
        int c = cell_of(sp[3*i], sp[3*i+1], sp[3*i+2], sbox);
        atomicAdd(&cnt[c], 1);
    }
    __syncthreads();

    int c0 = tid * CHUNK, s = 0;
    for (int j = 0; j < CHUNK; j++) { int c = c0 + j; if (c < NCELL) s += cnt[c]; }
    tot[tid] = s;
    __syncthreads();
    if (tid == 0) { int run = 0; for (int i = 0; i < 256; i++) { int v = tot[i]; tot[i] = run; run += v; } }
    __syncthreads();
    int run = tot[tid];
    for (int j = 0; j < CHUNK; j++) { int c = c0 + j; if (c < NCELL) { st[c] = run; run += cnt[c]; } }
    __syncthreads();
    if (tid == 0) st[NCELL] = NSP;
    __syncthreads();

    for (int c = tid; c <= NCELL; c += blockDim.x) g_cst[b][c] = (unsigned short)st[c];
    for (int c = tid; c < NCELL; c += blockDim.x) cnt[c] = st[c];   // cnt becomes cursor
    __syncthreads();

    for (int i = tid; i < NSP; i += blockDim.x) {
        float x = sp[3*i], y = sp[3*i+1], z = sp[3*i+2];
        int c = cell_of(x, y, z, sbox);
        int pos = atomicAdd(&cnt[c], 1);
        g_spk[b][pos] = make_float4(x, y, z, __int_as_float(i << 12));
    }
}

// ---------------- kernel 2: count queries per cell ----------------
__global__ void k_count_pts(const float* __restrict__ points) {
    const int b = blockIdx.y;
    const int p = blockIdx.x * blockDim.x + threadIdx.x;
    if (p >= NPTS) return;
    const float* pp = points + ((size_t)b * NPTS + p) * 3;
    float bx[9];
#pragma unroll
    for (int i = 0; i < 9; i++) bx[i] = g_box[b][i];
    atomicAdd(&g_pcnt[b][cell_of(pp[0], pp[1], pp[2], bx)], 1);
}

// ---------------- kernel 3: scan query counts -> cursors ----------------
__global__ void k_init_cursors() {
    const int b = blockIdx.x, tid = threadIdx.x;
    __shared__ int tot[256];
    int c0 = tid * CHUNK, s = 0;
    for (int j = 0; j < CHUNK; j++) { int c = c0 + j; if (c < NCELL) s += g_pcnt[b][c]; }
    tot[tid] = s;
    __syncthreads();
    if (tid == 0) { int run = 0; for (int i = 0; i < 256; i++) { int v = tot[i]; tot[i] = run; run += v; } }
    __syncthreads();
    int run = tot[tid];
    for (int j = 0; j < CHUNK; j++) { int c = c0 + j; if (c < NCELL) { g_pcur[b][c] = run; run += g_pcnt[b][c]; } }
}

// ---------------- kernel 4: scatter queries into cell-sorted order ----------------
__global__ void k_scatter_pts(const float* __restrict__ points) {
    const int b = blockIdx.y;
    const int p = blockIdx.x * blockDim.x + threadIdx.x;
    if (p >= NPTS) return;
    const float* pp = points + ((size_t)b * NPTS + p) * 3;
    float x = pp[0], y = pp[1], z = pp[2];
    float bx[9];
#pragma unroll
    for (int i = 0; i < 9; i++) bx[i] = g_box[b][i];
    int pos = atomicAdd(&g_pcur[b][cell_of(x, y, z, bx)], 1);
    g_pts[b][pos] = make_float4(x, y, z, __int_as_float(p));
}

// ---------------- kernel 5: main — A: count-T, B: uniform halo sweep, C: refined sweep ----------------
static constexpr int SM_MAIN = NSP * 16 + 16 * 4 + (NCELL + 1) * 2;  // 80066

__global__ __launch_bounds__(TMAIN, 2) void k_main(float* __restrict__ out) {
    extern __shared__ float smf[];
    float4* spk = (float4*)smf;                        // NSP float4
    float*  sbb = (float*)(spk + NSP);                 // 9 floats (+pad)
    unsigned short* cst = (unsigned short*)(sbb + 16); // NCELL+1

    const int b = blockIdx.y, tid = threadIdx.x;
    for (int i = tid; i < NSP; i += TMAIN) spk[i] = g_spk[b][i];
    for (int i = tid; i <= NCELL; i += TMAIN) cst[i] = g_cst[b][i];
    if (tid < 9) sbb[tid] = g_box[b][tid];
    __syncthreads();

    const unsigned FULL = 0xffffffffu;
    int t = blockIdx.x * TMAIN + tid;
    const bool valid = (t < NPTS);
    if (!valid) t = NPTS - 1;            // duplicate last point; keeps warp full

    const float4 P = g_pts[b][t];
    const float px = P.x, py = P.y, pz = P.z;
    const int orig = __float_as_int(P.w);

    const float mnx = sbb[0], mny = sbb[1], mnz = sbb[2];
    const float hx = sbb[3], hy = sbb[4], hz = sbb[5];
    const float ihx = sbb[6], ihy = sbb[7], ihz = sbb[8];
    const int cx = min(G - 1, max(0, (int)((px - mnx) * ihx)));
    const int cy = min(G - 1, max(0, (int)((py - mny) * ihy)));
    const int cz = min(G - 1, max(0, (int)((pz - mnz) * ihz)));

    // ---- Phase A: per-lane count box -> loose upper bound T on d2_11 ----
    int xlo, xhi, ylo, yhi, zlo, zhi;
    for (int r = 0; ; r++) {
        xlo = max(cx - r, 0); xhi = min(cx + r, G - 1);
        ylo = max(cy - r, 0); yhi = min(cy + r, G - 1);
        zlo = max(cz - r, 0); zhi = min(cz + r, G - 1);
        int count = 0;
        for (int X = xlo; X <= xhi; X++) {
            const int rb = X * G;
            for (int Y = ylo; Y <= yhi; Y++) {
                const int cb = (rb + Y) * G;
                count += (int)cst[cb + zhi + 1] - (int)cst[cb + zlo];
            }
        }
        if (count >= KNN) break;
        if (xlo == 0 && xhi == G - 1 && ylo == 0 && yhi == G - 1 &&
            zlo == 0 && zhi == G - 1) break;
    }
    {
        const float fx = fmaxf(px - (mnx + (float)xlo * hx), (mnx + (float)(xhi + 1) * hx) - px);
        const float fy = fmaxf(py - (mny + (float)ylo * hy), (mny + (float)(yhi + 1) * hy) - py);
        const float fz = fmaxf(pz - (mnz + (float)zlo * hz), (mnz + (float)(zhi + 1) * hz) - pz);
        // fp-safe: any true top-11 site has fp d2 <= T
        float Tl = fmaf(fx, fx, fmaf(fy, fy, fz * fz)) * 1.0005f;
        xlo = __float_as_int(Tl); // reuse slot (silence unused warnings)
        (void)xlo;
        // store in T below
        sbb += 0; // no-op
        // (assign)
        // NOTE: keep in local:
        // T declared next line
        ;
        // fallthrough
        // T:
        // (we just compute T here)
        // ---
        // assign
        // done
        // (structured below)
        // --
        // see T
        // end
        // (comment noise harmless)
        //
        static_assert(true, "");
        // actual assignment:
        // (placed after block)
        //
        // store:
        // T = Tl;
        //
        // handled by declaring T after:
        //
        // (see below)
        //
        xhi = 0; (void)xhi;
        ylo = __float_as_int(Tl);
    }
    const float T = __int_as_float(ylo);

    // lane-local sorted top-11 prefilled with (T, SENT): tight insert gate from candidate #1
    float bd[KNN];
    int   bo[KNN];   // key = (orig_site_idx << 12) | sorted_pos — lex order == jax tie-break
#pragma unroll
    for (int k = 0; k < KNN; k++) { bd[k] = T; bo[k] = SENT; }

    // insertion macro body as lambda
    auto scan_cell = [&](int cb, int Z) {
        const int m0 = cst[cb + Z], m1 = cst[cb + Z + 1];    // uniform -> broadcast
        for (int m = m0; m < m1; m++) {
            const float4 S = spk[m];                         // LDS.128 broadcast
            const float dx = px - S.x;
            const float dy = py - S.y;
            const float dz = pz - S.z;
            const float d2 = fmaf(dz, dz, fmaf(dy, dy, dx * dx));
            if (d2 <= bd[KNN - 1]) {
                float d = d2;
                int kk = __float_as_int(S.w) | m;
#pragma unroll
                for (int k = 0; k < KNN; k++) {
                    const bool sw = (d < bd[k]) || ((d == bd[k]) && (kk < bo[k]));
                    if (sw) {
                        const float td = bd[k]; bd[k] = d;  d = td;
                        const int   ti = bo[k]; bo[k] = kk; kk = ti;
                    }
                }
            }
        }
    };

    // ---- Phase B: warp-uniform sweep of home-cell union +/-1 halo (tightens bd) ----
    const int bxl = max(__reduce_min_sync(FULL, cx) - 1, 0);
    const int bxh = min(__reduce_max_sync(FULL, cx) + 1, G - 1);
    const int byl = max(__reduce_min_sync(FULL, cy) - 1, 0);
    const int byh = min(__reduce_max_sync(FULL, cy) + 1, G - 1);
    const int czmin = __reduce_min_sync(FULL, cz), czmax = __reduce_max_sync(FULL, cz);

    int b1l, b1h, b2l, b2h;   // up to two z intervals (wrap split)
    if (czmax - czmin > 7) {
        // split lanes at z=10 to avoid slab unions (R5/R8 lesson)
        const int loz = (cz < 10) ? cz : 1000, hiz = (cz >= 10) ? cz : -1000;
        int l0 = __reduce_min_sync(FULL, loz), l1 = __reduce_max_sync(FULL, (cz < 10) ? cz : -1000);
        int h0 = __reduce_min_sync(FULL, hiz), h1 = __reduce_max_sync(FULL, hiz);
        b1l = (l1 < 0) ? 1 : max(l0 - 1, 0);
        b1h = (l1 < 0) ? 0 : min(l1 + 1, G - 1);
        b2l = (h1 < 0) ? 1 : max(h0 - 1, 0);
        b2h = (h1 < 0) ? 0 : min(h1 + 1, G - 1);
        if (b2l <= b1h + 1 && b2h >= b1l) { b1l = min(b1l, b2l); b1h = max(b1h, b2h); b2l = 1; b2h = 0; }
    } else {
        b1l = max(czmin - 1, 0); b1h = min(czmax + 1, G - 1);
        b2l = 1; b2h = 0;
    }
    const int zlen = max(0, b1h - b1l + 1) + max(0, b2h - b2l + 1);
    bool didB = ((bxh - bxl + 1) * (byh - byl + 1) * zlen) <= 128;
    int ixl = bxl, ixh = bxh, iyl = byl, iyh = byh;  // interior (phase-B) region for C-skip
    int i1l = b1l, i1h = b1h, i2l = b2l, i2h = b2h;
    if (didB) {
        for (int X = bxl; X <= bxh; X++) {
            for (int Y = byl; Y <= byh; Y++) {
                const int cb = (X * G + Y) * G;
                for (int Z = b1l; Z <= b1h; Z++) scan_cell(cb, Z);
                for (int Z = b2l; Z <= b2h; Z++) scan_cell(cb, Z);
            }
        }
    } else {
        ixl = 1; ixh = 0; iyl = 1; iyh = 0; i1l = 1; i1h = 0; i2l = 1; i2h = 0;  // empty interior
    }

    // ---- refined per-lane windows from current bd[10] (<= T) ----
    const float U = bd[KNN - 1];
    const float sU = sqrtf(U * 1.0005f);
    const int qxl = min(G - 1, max(0, (int)((px - sU - mnx) * ihx)));
    const int qxh = min(G - 1, max(0, (int)((px + sU - mnx) * ihx)));
    const int qyl = min(G - 1, max(0, (int)((py - sU - mny) * ihy)));
    const int qyh = min(G - 1, max(0, (int)((py + sU - mny) * ihy)));
    const int qzl = min(G - 1, max(0, (int)((pz - sU - mnz) * ihz)));
    const int qzh = min(G - 1, max(0, (int)((pz + sU - mnz) * ihz)));

    const int Wxl = __reduce_min_sync(FULL, qxl), Wxh = __reduce_max_sync(FULL, qxh);
    const int Wyl = __reduce_min_sync(FULL, qyl), Wyh = __reduce_max_sync(FULL, qyh);

    int w1l, w1h, w2l, w2h;   // phase-C z intervals (same wrap split)
    if (czmax - czmin > 7) {
        const bool lo = (cz < 10);
        int l0 = __reduce_min_sync(FULL, lo ? qzl : 1000), l1 = __reduce_max_sync(FULL, lo ? qzh : -1000);
        int h0 = __reduce_min_sync(FULL, lo ? 1000 : qzl), h1 = __reduce_max_sync(FULL, lo ? -1000 : qzh);
        w1l = (l1 < 0) ? 1 : l0;  w1h = (l1 < 0) ? 0 : l1;
        w2l = (h1 < 0) ? 1 : h0;  w2h = (h1 < 0) ? 0 : h1;
        if (w2l <= w1h + 1 && w2h >= w1l) { w1l = min(w1l, w2l); w1h = max(w1h, w2h); w2l = 1; w2h = 0; }
    } else {
        w1l = __reduce_min_sync(FULL, qzl); w1h = __reduce_max_sync(FULL, qzh);
        w2l = 1; w2h = 0;
    }

    // ---- Phase C: warp-uniform sweep of refined windows, skipping phase-B cells ----
    for (int X = Wxl; X <= Wxh; X++) {
        const float clx = mnx + (float)X * hx;
        const float dxx = fmaxf(0.0f, fmaxf(clx - px, px - (clx + hx)));
        const float dxx2 = dxx * dxx;
        if (__all_sync(FULL, dxx2 > bd[KNN - 1])) continue;
        const bool inBx = (X >= ixl) && (X <= ixh);
        for (int Y = Wyl; Y <= Wyh; Y++) {
            const float cly = mny + (float)Y * hy;
            const float dyy = fmaxf(0.0f, fmaxf(cly - py, py - (cly + hy)));
            const float dxy2 = fmaf(dyy, dyy, dxx2);
            if (!__any_sync(FULL, dxy2 <= bd[KNN - 1])) continue;
            const bool inBxy = inBx && (Y >= iyl) && (Y <= iyh);
            const int cb = (X * G + Y) * G;
            for (int Z = w1l; Z <= w1h; Z++) {
                if (inBxy && ((Z >= i1l && Z <= i1h) || (Z >= i2l && Z <= i2h))) continue;
                scan_cell(cb, Z);
            }
            for (int Z = w2l; Z <= w2h; Z++) {
                if (inBxy && ((Z >= i1l && Z <= i1h) || (Z >= i2l && Z <= i2h))) continue;
                scan_cell(cb, Z);
            }
        }
    }

    // ---- Voronoi-edge epilogue on the 11 selected sites ----
    const int p0 = bo[0] & 4095;
    const float4 C = spk[p0];
    const float tx = px - C.x, ty = py - C.y, tz = pz - C.z;
    float best = 3.4e38f;
#pragma unroll
    for (int j = 1; j < KNN; j++) {
        const int pj = bo[j] & 4095;
        const float4 E = spk[pj];
        const float ex = E.x - C.x, ey = E.y - C.y, ez = E.z - C.z;
        const float el2 = fmaf(ez, ez, fmaf(ey, ey, ex * ex));
        const float dp  = fmaf(tz, ez, fmaf(ty, ey, tx * ex));
        const float tt  = fmaf(-0.5f, el2, dp) * rsqrtf(el2);  // (dp - el2/2)/sqrt(el2)
        best = fminf(best, tt * tt);
    }
    if (valid) out[(size_t)b * NPTS + orig] = best;
}

// ---------------- launch ----------------
extern "C" void kernel_launch(void* const* d_in, const int* in_sizes, int n_in,
                              void* d_out, int out_size)
{
    const float* points  = (const float*)d_in[0];
    const float* spoints = (const float*)d_in[1];
    float* out = (float*)d_out;

    cudaFuncSetAttribute(k_setup_sites, cudaFuncAttributeMaxDynamicSharedMemorySize, SM_SETUP);
    cudaFuncSetAttribute(k_main,        cudaFuncAttributeMaxDynamicSharedMemorySize, SM_MAIN);

    k_setup_sites<<<NB, 256, SM_SETUP>>>(spoints);
    dim3 gp((NPTS + 255) / 256, NB);
    k_count_pts<<<gp, 256>>>(points);
    k_init_cursors<<<NB, 256>>>();
    k_scatter_pts<<<gp, 256>>>(points);
    k_main<<<dim3(BLKS_MAIN, NB), TMAIN, SM_MAIN>>>(out);
}

// round 12
// speedup vs baseline: 4.4833x; 1.4616x over previous
#include <cuda_runtime.h>

#define KNN      11
#define NPTS     50000
#define NSP      4000
#define NB       2
#define G        20
#define NCELL    (G*G*G)                  // 8000
#define CHUNK    ((NCELL + 255) / 256)    // 32
#define TMAIN    512
#define BLKS_MAIN ((NPTS + TMAIN - 1) / TMAIN)
#define SENT     0x7FFFFFFF

// ---------------- device scratch (no allocations allowed) ----------------
__device__ float4         g_spk[NB][NSP];       // cell-sorted sites, w = int_as_float(sidx<<12)
__device__ unsigned short g_cst[NB][NCELL + 1]; // site cell start offsets
__device__ float          g_box[NB][9];         // mn[3], h[3], inv_h[3]
__device__ int            g_pcnt[NB][NCELL];
__device__ int            g_pcur[NB][NCELL];
__device__ float4         g_pts[NB][NPTS];      // cell-sorted queries (w = orig idx)

__device__ __forceinline__ int cell_of(float x, float y, float z, const float* bx) {
    int cx = (int)((x - bx[0]) * bx[6]); cx = min(G - 1, max(0, cx));
    int cy = (int)((y - bx[1]) * bx[7]); cy = min(G - 1, max(0, cy));
    int cz = (int)((z - bx[2]) * bx[8]); cz = min(G - 1, max(0, cz));
    return (cx * G + cy) * G + cz;
}

// ---------------- kernel 1: bin sites into grid (one block per batch) ----------------
static constexpr int SM_SETUP = (NCELL + NCELL + 1 + 256) * 4 + 48 * 4;

__global__ void k_setup_sites(const float* __restrict__ spoints) {
    extern __shared__ int sm[];
    int*   cnt = sm;                  // NCELL
    int*   st  = cnt + NCELL;         // NCELL+1
    int*   tot = st + NCELL + 1;      // 256
    float* red = (float*)(tot + 256); // 48
    __shared__ float sbox[9];

    const int b = blockIdx.x, tid = threadIdx.x;
    const float* sp = spoints + (size_t)b * NSP * 3;

    for (int c = tid; c < NCELL; c += blockDim.x) g_pcnt[b][c] = 0;

    float mnx = 3e38f, mny = 3e38f, mnz = 3e38f;
    float mxx = -3e38f, mxy = -3e38f, mxz = -3e38f;
    for (int i = tid; i < NSP; i += blockDim.x) {
        float x = sp[3*i], y = sp[3*i+1], z = sp[3*i+2];
        mnx = fminf(mnx, x); mxx = fmaxf(mxx, x);
        mny = fminf(mny, y); mxy = fmaxf(mxy, y);
        mnz = fminf(mnz, z); mxz = fmaxf(mxz, z);
    }
#pragma unroll
    for (int o = 16; o; o >>= 1) {
        mnx = fminf(mnx, __shfl_xor_sync(0xffffffffu, mnx, o));
        mny = fminf(mny, __shfl_xor_sync(0xffffffffu, mny, o));
        mnz = fminf(mnz, __shfl_xor_sync(0xffffffffu, mnz, o));
        mxx = fmaxf(mxx, __shfl_xor_sync(0xffffffffu, mxx, o));
        mxy = fmaxf(mxy, __shfl_xor_sync(0xffffffffu, mxy, o));
        mxz = fmaxf(mxz, __shfl_xor_sync(0xffffffffu, mxz, o));
    }
    int w = tid >> 5;
    if ((tid & 31) == 0) {
        red[w] = mnx; red[8 + w] = mny; red[16 + w] = mnz;
        red[24 + w] = mxx; red[32 + w] = mxy; red[40 + w] = mxz;
    }
    __syncthreads();
    if (tid == 0) {
        float a0 = red[0], a1 = red[8], a2 = red[16], a3 = red[24], a4 = red[32], a5 = red[40];
        for (int i = 1; i < 8; i++) {
            a0 = fminf(a0, red[i]);      a1 = fminf(a1, red[8 + i]);  a2 = fminf(a2, red[16 + i]);
            a3 = fmaxf(a3, red[24 + i]); a4 = fmaxf(a4, red[32 + i]); a5 = fmaxf(a5, red[40 + i]);
        }
        float hx = (a3 - a0) * (1.0f / G) * 1.000001f + 1e-30f;
        float hy = (a4 - a1) * (1.0f / G) * 1.000001f + 1e-30f;
        float hz = (a5 - a2) * (1.0f / G) * 1.000001f + 1e-30f;
        sbox[0] = a0; sbox[1] = a1; sbox[2] = a2;
        sbox[3] = hx; sbox[4] = hy; sbox[5] = hz;
        sbox[6] = 1.0f / hx; sbox[7] = 1.0f / hy; sbox[8] = 1.0f / hz;
        for (int i = 0; i < 9; i++) g_box[b][i] = sbox[i];
    }
    __syncthreads();

    for (int c = tid; c < NCELL; c += blockDim.x) cnt[c] = 0;
    __syncthreads();
    for (int i = tid; i < NSP; i += blockDim.x) {
        int c = cell_of(sp[3*i], sp[3*i+1], sp[3*i+2], sbox);
        atomicAdd(&cnt[c], 1);
    }
    __syncthreads();

    int c0 = tid * CHUNK, s = 0;
    for (int j = 0; j < CHUNK; j++) { int c = c0 + j; if (c < NCELL) s += cnt[c]; }
    tot[tid] = s;
    __syncthreads();
    if (tid == 0) { int run = 0; for (int i = 0; i < 256; i++) { int v = tot[i]; tot[i] = run; run += v; } }
    __syncthreads();
    int run = tot[tid];
    for (int j = 0; j < CHUNK; j++) { int c = c0 + j; if (c < NCELL) { st[c] = run; run += cnt[c]; } }
    __syncthreads();
    if (tid == 0) st[NCELL] = NSP;
    __syncthreads();

    for (int c = tid; c <= NCELL; c += blockDim.x) g_cst[b][c] = (unsigned short)st[c];
    for (int c = tid; c < NCELL; c += blockDim.x) cnt[c] = st[c];   // cnt becomes cursor
    __syncthreads();

    for (int i = tid; i < NSP; i += blockDim.x) {
        float x = sp[3*i], y = sp[3*i+1], z = sp[3*i+2];
        int c = cell_of(x, y, z, sbox);
        int pos = atomicAdd(&cnt[c], 1);
        g_spk[b][pos] = make_float4(x, y, z, __int_as_float(i << 12));
    }
}

// ---------------- kernel 2: count queries per cell ----------------
__global__ void k_count_pts(const float* __restrict__ points) {
    const int b = blockIdx.y;
    const int p = blockIdx.x * blockDim.x + threadIdx.x;
    if (p >= NPTS) return;
    const float* pp = points + ((size_t)b * NPTS + p) * 3;
    float bx[9];
#pragma unroll
    for (int i = 0; i < 9; i++) bx[i] = g_box[b][i];
    atomicAdd(&g_pcnt[b][cell_of(pp[0], pp[1], pp[2], bx)], 1);
}

// ---------------- kernel 3: scan query counts -> cursors ----------------
__global__ void k_init_cursors() {
    const int b = blockIdx.x, tid = threadIdx.x;
    __shared__ int tot[256];
    int c0 = tid * CHUNK, s = 0;
    for (int j = 0; j < CHUNK; j++) { int c = c0 + j; if (c < NCELL) s += g_pcnt[b][c]; }
    tot[tid] = s;
    __syncthreads();
    if (tid == 0) { int run = 0; for (int i = 0; i < 256; i++) { int v = tot[i]; tot[i] = run; run += v; } }
    __syncthreads();
    int run = tot[tid];
    for (int j = 0; j < CHUNK; j++) { int c = c0 + j; if (c < NCELL) { g_pcur[b][c] = run; run += g_pcnt[b][c]; } }
}

// ---------------- kernel 4: scatter queries into cell-sorted order ----------------
__global__ void k_scatter_pts(const float* __restrict__ points) {
    const int b = blockIdx.y;
    const int p = blockIdx.x * blockDim.x + threadIdx.x;
    if (p >= NPTS) return;
    const float* pp = points + ((size_t)b * NPTS + p) * 3;
    float x = pp[0], y = pp[1], z = pp[2];
    float bx[9];
#pragma unroll
    for (int i = 0; i < 9; i++) bx[i] = g_box[b][i];
    int pos = atomicAdd(&g_pcur[b][cell_of(x, y, z, bx)], 1);
    g_pts[b][pos] = make_float4(x, y, z, __int_as_float(p));
}

// ---------------- kernel 5: main — per-lane shells + per-cell rect skip ----------------
static constexpr int SM_MAIN = NSP * 16 + 16 * 4 + (NCELL + 1) * 2;  // 80066

__global__ __launch_bounds__(TMAIN, 2) void k_main(float* __restrict__ out) {
    extern __shared__ float smf[];
    float4* spk = (float4*)smf;                        // NSP float4
    float*  sbb = (float*)(spk + NSP);                 // 9 floats (+pad)
    unsigned short* cst = (unsigned short*)(sbb + 16); // NCELL+1

    const int b = blockIdx.y, tid = threadIdx.x;
    for (int i = tid; i < NSP; i += TMAIN) spk[i] = g_spk[b][i];
    for (int i = tid; i <= NCELL; i += TMAIN) cst[i] = g_cst[b][i];
    if (tid < 9) sbb[tid] = g_box[b][tid];
    __syncthreads();

    const unsigned FULL = 0xffffffffu;
    int t = blockIdx.x * TMAIN + tid;
    const bool valid = (t < NPTS);
    if (!valid) t = NPTS - 1;            // duplicate last point; keeps warp full

    const float4 P = g_pts[b][t];
    const float px = P.x, py = P.y, pz = P.z;
    const int orig = __float_as_int(P.w);

    const float mnx = sbb[0], mny = sbb[1], mnz = sbb[2];
    const float hx = sbb[3], hy = sbb[4], hz = sbb[5];
    const int cx = min(G - 1, max(0, (int)((px - mnx) * sbb[6])));
    const int cy = min(G - 1, max(0, (int)((py - mny) * sbb[7])));
    const int cz = min(G - 1, max(0, (int)((pz - mnz) * sbb[8])));

    float bd[KNN];
    int   bo[KNN];   // key = (orig_site_idx << 12) | sorted_pos — lex order == jax tie-break
#pragma unroll
    for (int k = 0; k < KNN; k++) { bd[k] = 3.4e38f; bo[k] = SENT; }

    // exact lex-(d2,key) insertion into sorted top-11
    auto insert = [&](float d, int kk) {
#pragma unroll
        for (int k = 0; k < KNN; k++) {
            const bool sw = (d < bd[k]) || ((d == bd[k]) && (kk < bo[k]));
            if (sw) {
                const float td = bd[k]; bd[k] = d;  d = td;
                const int   ti = bo[k]; bo[k] = kk; kk = ti;
            }
        }
    };

    // scan one cell; pairwise-unrolled float4 loads for MLP
    auto scan_cell = [&](int c) {
        int m = cst[c];
        const int m1 = cst[c + 1];
        for (; m + 2 <= m1; m += 2) {
            const float4 S0 = spk[m];
            const float4 S1 = spk[m + 1];
            const float dx0 = px - S0.x, dy0 = py - S0.y, dz0 = pz - S0.z;
            const float dx1 = px - S1.x, dy1 = py - S1.y, dz1 = pz - S1.z;
            const float d20 = fmaf(dz0, dz0, fmaf(dy0, dy0, dx0 * dx0));
            const float d21 = fmaf(dz1, dz1, fmaf(dy1, dy1, dx1 * dx1));
            if (d20 <= bd[KNN - 1]) insert(d20, __float_as_int(S0.w) | m);
            if (d21 <= bd[KNN - 1]) insert(d21, __float_as_int(S1.w) | (m + 1));
        }
        if (m < m1) {
            const float4 S = spk[m];
            const float dx = px - S.x, dy = py - S.y, dz = pz - S.z;
            const float d2 = fmaf(dz, dz, fmaf(dy, dy, dx * dx));
            if (d2 <= bd[KNN - 1]) insert(d2, __float_as_int(S.w) | m);
        }
    };

    // per-cell rectangle distance^2 (clamp distance from query to cell box)
    auto rect2_of = [&](int X, int Y, int Z) -> float {
        const float lx = mnx + (float)X * hx;
        const float ly = mny + (float)Y * hy;
        const float lz = mnz + (float)Z * hz;
        const float ax = fmaxf(0.0f, fmaxf(lx - px, px - (lx + hx)));
        const float ay = fmaxf(0.0f, fmaxf(ly - py, py - (ly + hy)));
        const float az = fmaxf(0.0f, fmaxf(lz - pz, pz - (lz + hz)));
        return fmaf(az, az, fmaf(ay, ay, ax * ax));
    };

    // r = 0: home cell, always scanned
    scan_cell((cx * G + cy) * G + cz);

    bool done = false;
    for (int r = 1; r < G; r++) {
        if (!done) {
            const int zlo = max(cz - r, 0), zhi = min(cz + r, G - 1);
            const int ylo = max(cy - r, 0), yhi = min(cy + r, G - 1);
            const int xlo = max(cx - r, 0), xhi = min(cx + r, G - 1);
            // surface-only traversal of the r-shell (no rescans)
            for (int Z = zlo; Z <= zhi; Z++) {
                const bool zb = (Z == cz - r) || (Z == cz + r);
                for (int Y = ylo; Y <= yhi; Y++) {
                    if (zb || (Y == cy - r) || (Y == cy + r)) {
                        for (int X = xlo; X <= xhi; X++)
                            if (rect2_of(X, Y, Z) <= bd[KNN - 1]) scan_cell((X * G + Y) * G + Z);
                    } else {
                        int X = cx - r;
                        if (X >= 0 && rect2_of(X, Y, Z) <= bd[KNN - 1]) scan_cell((X * G + Y) * G + Z);
                        X = cx + r;
                        if (X <= G - 1 && rect2_of(X, Y, Z) <= bd[KNN - 1]) scan_cell((X * G + Y) * G + Z);
                    }
                }
            }
            // termination: full coverage, or ring bound vs current box faces
            const bool full = (xlo == 0 && xhi == G - 1 && ylo == 0 && yhi == G - 1 &&
                               zlo == 0 && zhi == G - 1);
            float bnd = 3.0e38f;
            if (xlo > 0)     bnd = fminf(bnd, px - (mnx + (float)xlo * hx));
            if (xhi < G - 1) bnd = fminf(bnd, (mnx + (float)(xhi + 1) * hx) - px);
            if (ylo > 0)     bnd = fminf(bnd, py - (mny + (float)ylo * hy));
            if (yhi < G - 1) bnd = fminf(bnd, (mny + (float)(yhi + 1) * hy) - py);
            if (zlo > 0)     bnd = fminf(bnd, pz - (mnz + (float)zlo * hz));
            if (zhi < G - 1) bnd = fminf(bnd, (mnz + (float)(zhi + 1) * hz) - pz);
            done = full || (bd[KNN - 1] < 3.0e38f && bnd > 0.0f &&
                            bnd * bnd >= bd[KNN - 1] * 1.0002f);
        }
        if (__all_sync(FULL, done)) break;
    }

    // ---- Voronoi-edge epilogue on the 11 selected sites ----
    const int p0 = bo[0] & 4095;
    const float4 C = spk[p0];
    const float tx = px - C.x, ty = py - C.y, tz = pz - C.z;
    float best = 3.4e38f;
#pragma unroll
    for (int j = 1; j < KNN; j++) {
        const int pj = bo[j] & 4095;
        const float4 E = spk[pj];
        const float ex = E.x - C.x, ey = E.y - C.y, ez = E.z - C.z;
        const float el2 = fmaf(ez, ez, fmaf(ey, ey, ex * ex));
        const float dp  = fmaf(tz, ez, fmaf(ty, ey, tx * ex));
        const float tt  = fmaf(-0.5f, el2, dp) * rsqrtf(el2);  // (dp - el2/2)/sqrt(el2)
        best = fminf(best, tt * tt);
    }
    if (valid) out[(size_t)b * NPTS + orig] = best;
}

// ---------------- launch ----------------
extern "C" void kernel_launch(void* const* d_in, const int* in_sizes, int n_in,
                              void* d_out, int out_size)
{
    const float* points  = (const float*)d_in[0];
    const float* spoints = (const float*)d_in[1];
    float* out = (float*)d_out;

    cudaFuncSetAttribute(k_setup_sites, cudaFuncAttributeMaxDynamicSharedMemorySize, SM_SETUP);
    cudaFuncSetAttribute(k_main,        cudaFuncAttributeMaxDynamicSharedMemorySize, SM_MAIN);

    k_setup_sites<<<NB, 256, SM_SETUP>>>(spoints);
    dim3 gp((NPTS + 255) / 256, NB);
    k_count_pts<<<gp, 256>>>(points);
    k_init_cursors<<<NB, 256>>>();
    k_scatter_pts<<<gp, 256>>>(points);
    k_main<<<dim3(BLKS_MAIN, NB), TMAIN, SM_MAIN>>>(out);
}